// round 6
// baseline (speedup 1.0000x reference)
#include <cuda_runtime.h>
#include <math.h>

// 9x9 max-dilation, SAME padding with -inf border. Fully fused, smem-free
// data path:
//   - block tile = 1024 (full width) x 8 output rows; 8 warps x 32 lanes x 4 cols
//   - vertical 9-max: Gil-Werman in registers (suffix array rows 0-8 +
//     running prefix rows 9-15), float4 per lane
//   - horizontal 9-max: prefix/suffix + warp shuffles; cross-warp edge
//     columns exchanged via a tiny smem buffer (one __syncthreads)
// Input 16x1024x1024x1 fp32.

#define IMG 1024
#define TH 8              // output rows per block
#define NTH 256
#define NW 8              // warps per block (8 x 128 cols = 1024)

__device__ __forceinline__ float4 max4(float4 a, float4 b) {
    return make_float4(fmaxf(a.x, b.x), fmaxf(a.y, b.y),
                       fmaxf(a.z, b.z), fmaxf(a.w, b.w));
}

__global__ __launch_bounds__(NTH)
void dilate9_kernel(const float* __restrict__ in, float* __restrict__ out) {
    __shared__ __align__(16) float4 edgeL[NW][TH];  // lane 0's vmax per warp/row
    __shared__ __align__(16) float4 edgeR[NW][TH];  // lane 31's vmax per warp/row

    const int strip = blockIdx.x;     // 0..127 (8-row strips)
    const int bz    = blockIdx.y;     // batch
    const int tid   = threadIdx.x;
    const int lane  = tid & 31;
    const int w     = tid >> 5;

    const float* img = in  + (size_t)bz * IMG * IMG;
    float*      oimg = out + (size_t)bz * IMG * IMG;

    const int gx  = w * 128 + lane * 4;   // first of this thread's 4 cols
    const int gy0 = strip * TH - 4;       // first raw row

    const float4 NEGF4 = make_float4(-INFINITY, -INFINITY, -INFINITY, -INFINITY);

    // ---- Vertical 9-max (Gil-Werman, chunk of 9) ----
    // raw rows j = 0..15; out row t = max(raw rows t..t+8), t = 0..7
    float4 A[9];
    #pragma unroll
    for (int j = 0; j < 9; j++) {
        const int gy = gy0 + j;
        A[j] = ((unsigned)gy < (unsigned)IMG)
                 ? *(const float4*)(img + (size_t)gy * IMG + gx) : NEGF4;
    }
    // suffix maxes in place: A[j] = max(raw rows j..8)
    #pragma unroll
    for (int j = 7; j >= 0; j--) A[j] = max4(A[j], A[j + 1]);

    float4 vm[TH];
    vm[0] = A[0];                      // rows 0..8
    float4 preB = NEGF4;               // running max of rows 9..t+8
    #pragma unroll
    for (int t = 1; t < TH; t++) {
        const int gy = gy0 + t + 8;
        float4 r = ((unsigned)gy < (unsigned)IMG)
                     ? *(const float4*)(img + (size_t)gy * IMG + gx) : NEGF4;
        preB = max4(preB, r);
        vm[t] = max4(A[t], preB);
    }

    // ---- cross-warp edge exchange ----
    if (lane == 0) {
        #pragma unroll
        for (int t = 0; t < TH; t++) edgeL[w][t] = vm[t];
    }
    if (lane == 31) {
        #pragma unroll
        for (int t = 0; t < TH; t++) edgeR[w][t] = vm[t];
    }
    __syncthreads();

    // ---- Horizontal 9-max via prefix/suffix + shuffles, then STG.128 ----
    #pragma unroll
    for (int t = 0; t < TH; t++) {
        const float4 v = vm[t];
        const float p0 = v.x;
        const float p1 = fmaxf(p0, v.y);
        const float p2 = fmaxf(p1, v.z);
        const float p3 = fmaxf(p2, v.w);
        const float s3 = v.w;
        const float s2 = fmaxf(v.z, s3);
        const float s1 = fmaxf(v.y, s2);
        const float s0 = p3;

        float sU0 = __shfl_up_sync(0xffffffffu, s0, 1);
        float sU1 = __shfl_up_sync(0xffffffffu, s1, 1);
        float sU2 = __shfl_up_sync(0xffffffffu, s2, 1);
        float sU3 = __shfl_up_sync(0xffffffffu, s3, 1);
        float pD0 = __shfl_down_sync(0xffffffffu, p0, 1);
        float pD1 = __shfl_down_sync(0xffffffffu, p1, 1);
        float pD2 = __shfl_down_sync(0xffffffffu, p2, 1);
        float pD3 = __shfl_down_sync(0xffffffffu, p3, 1);

        if (lane == 0) {   // left neighbor group = warp w-1, lane 31 (or border)
            const float4 hl = (w > 0) ? edgeR[w - 1][t] : NEGF4;
            sU3 = hl.w;
            sU2 = fmaxf(hl.z, sU3);
            sU1 = fmaxf(hl.y, sU2);
            sU0 = fmaxf(hl.x, sU1);
        }
        if (lane == 31) {  // right neighbor group = warp w+1, lane 0 (or border)
            const float4 hr = (w < NW - 1) ? edgeL[w + 1][t] : NEGF4;
            pD0 = hr.x;
            pD1 = fmaxf(pD0, hr.y);
            pD2 = fmaxf(pD1, hr.z);
            pD3 = fmaxf(pD2, hr.w);
        }

        float4 o;
        o.x = fmaxf(fmaxf(sU0, s0), pD0);
        o.y = fmaxf(fmaxf(sU1, s0), pD1);
        o.z = fmaxf(fmaxf(sU2, s0), pD2);
        o.w = fmaxf(fmaxf(sU3, s0), pD3);
        *(float4*)(oimg + (size_t)(strip * TH + t) * IMG + gx) = o;
    }
}

extern "C" void kernel_launch(void* const* d_in, const int* in_sizes, int n_in,
                              void* d_out, int out_size) {
    const float* in = (const float*)d_in[0];
    float* out = (float*)d_out;
    const int batch = in_sizes[0] / (IMG * IMG);
    dim3 grid(IMG / TH, batch);
    dilate9_kernel<<<grid, NTH>>>(in, out);
}

// round 7
// speedup vs baseline: 1.0177x; 1.0177x over previous
#include <cuda_runtime.h>
#include <math.h>

// 9x9 max-dilation, SAME padding with -inf border. Fused, smem-free data path,
// register-lean via two 4-row Gil-Werman chunks per block:
//   - block tile = 1024 (full width) x 8 output rows; 8 warps x 32 lanes x 4 cols
//   - per chunk: suffix maxes over 8 raw rows + streamed prefix over 4 more
//     -> 4 vertical-max rows in registers
//   - horizontal 9-max: prefix/suffix + warp shuffles; cross-warp edges via
//     double-buffered 2KB smem (one __syncthreads per chunk)
// Input 16x1024x1024x1 fp32.

#define IMG 1024
#define TH 8              // output rows per block
#define CH 4              // output rows per chunk
#define NTH 256
#define NW 8              // warps per block (8 x 128 cols = 1024)

__device__ __forceinline__ float4 max4(float4 a, float4 b) {
    return make_float4(fmaxf(a.x, b.x), fmaxf(a.y, b.y),
                       fmaxf(a.z, b.z), fmaxf(a.w, b.w));
}

__global__ __launch_bounds__(NTH, 5)
void dilate9_kernel(const float* __restrict__ in, float* __restrict__ out) {
    __shared__ __align__(16) float4 eL[2][NW][CH];  // lane 0 vmax, per chunk
    __shared__ __align__(16) float4 eR[2][NW][CH];  // lane 31 vmax, per chunk

    const int strip = blockIdx.x;     // 0..127 (8-row strips)
    const int bz    = blockIdx.y;     // batch
    const int tid   = threadIdx.x;
    const int lane  = tid & 31;
    const int w     = tid >> 5;

    const float* img = in  + (size_t)bz * IMG * IMG;
    float*      oimg = out + (size_t)bz * IMG * IMG;

    const int gx = w * 128 + lane * 4;    // first of this thread's 4 cols
    const float4 NEGF4 = make_float4(-INFINITY, -INFINITY, -INFINITY, -INFINITY);

    #pragma unroll
    for (int c = 0; c < 2; c++) {
        const int base = strip * TH + c * CH - 4;   // first raw row of chunk

        // ---- vertical: suffix maxes over raw rows base..base+7 ----
        float4 r[8];
        #pragma unroll
        for (int j = 0; j < 8; j++) {
            const int gy = base + j;
            r[j] = ((unsigned)gy < (unsigned)IMG)
                     ? *(const float4*)(img + (size_t)gy * IMG + gx) : NEGF4;
        }
        const float4 m47 = max4(max4(r[4], r[5]), max4(r[6], r[7]));
        const float4 S3 = max4(r[3], m47);   // rows 3..7
        const float4 S2 = max4(r[2], S3);    // rows 2..7
        const float4 S1 = max4(r[1], S2);    // rows 1..7
        const float4 S0 = max4(r[0], S1);    // rows 0..7

        // ---- vertical: streamed prefix over raw rows base+8..base+11 ----
        float4 vm[CH];
        {
            int gy = base + 8;
            float4 q = ((unsigned)gy < (unsigned)IMG)
                         ? *(const float4*)(img + (size_t)gy * IMG + gx) : NEGF4;
            vm[0] = max4(S0, q);                     // rows 0..8
            gy = base + 9;
            float4 n = ((unsigned)gy < (unsigned)IMG)
                         ? *(const float4*)(img + (size_t)gy * IMG + gx) : NEGF4;
            q = max4(q, n);
            vm[1] = max4(S1, q);                     // rows 1..9
            gy = base + 10;
            n = ((unsigned)gy < (unsigned)IMG)
                  ? *(const float4*)(img + (size_t)gy * IMG + gx) : NEGF4;
            q = max4(q, n);
            vm[2] = max4(S2, q);                     // rows 2..10
            gy = base + 11;
            n = ((unsigned)gy < (unsigned)IMG)
                  ? *(const float4*)(img + (size_t)gy * IMG + gx) : NEGF4;
            q = max4(q, n);
            vm[3] = max4(S3, q);                     // rows 3..11
        }

        // ---- cross-warp edge exchange (double-buffered by chunk) ----
        if (lane == 0) {
            #pragma unroll
            for (int t = 0; t < CH; t++) eL[c][w][t] = vm[t];
        }
        if (lane == 31) {
            #pragma unroll
            for (int t = 0; t < CH; t++) eR[c][w][t] = vm[t];
        }
        __syncthreads();

        // ---- horizontal 9-max via prefix/suffix + shuffles, STG.128 ----
        #pragma unroll
        for (int t = 0; t < CH; t++) {
            const float4 v = vm[t];
            const float p0 = v.x;
            const float p1 = fmaxf(p0, v.y);
            const float p2 = fmaxf(p1, v.z);
            const float p3 = fmaxf(p2, v.w);
            const float s3 = v.w;
            const float s2 = fmaxf(v.z, s3);
            const float s1 = fmaxf(v.y, s2);
            const float s0 = p3;

            float sU0 = __shfl_up_sync(0xffffffffu, s0, 1);
            float sU1 = __shfl_up_sync(0xffffffffu, s1, 1);
            float sU2 = __shfl_up_sync(0xffffffffu, s2, 1);
            float sU3 = __shfl_up_sync(0xffffffffu, s3, 1);
            float pD0 = __shfl_down_sync(0xffffffffu, p0, 1);
            float pD1 = __shfl_down_sync(0xffffffffu, p1, 1);
            float pD2 = __shfl_down_sync(0xffffffffu, p2, 1);
            float pD3 = __shfl_down_sync(0xffffffffu, p3, 1);

            if (lane == 0) {   // left neighbor = warp w-1 lane 31 (or border)
                const float4 hl = (w > 0) ? eR[c][w - 1][t] : NEGF4;
                sU3 = hl.w;
                sU2 = fmaxf(hl.z, sU3);
                sU1 = fmaxf(hl.y, sU2);
                sU0 = fmaxf(hl.x, sU1);
            }
            if (lane == 31) {  // right neighbor = warp w+1 lane 0 (or border)
                const float4 hr = (w < NW - 1) ? eL[c][w + 1][t] : NEGF4;
                pD0 = hr.x;
                pD1 = fmaxf(pD0, hr.y);
                pD2 = fmaxf(pD1, hr.z);
                pD3 = fmaxf(pD2, hr.w);
            }

            float4 o;
            o.x = fmaxf(fmaxf(sU0, s0), pD0);
            o.y = fmaxf(fmaxf(sU1, s0), pD1);
            o.z = fmaxf(fmaxf(sU2, s0), pD2);
            o.w = fmaxf(fmaxf(sU3, s0), pD3);
            *(float4*)(oimg + (size_t)(strip * TH + c * CH + t) * IMG + gx) = o;
        }
    }
}

extern "C" void kernel_launch(void* const* d_in, const int* in_sizes, int n_in,
                              void* d_out, int out_size) {
    const float* in = (const float*)d_in[0];
    float* out = (float*)d_out;
    const int batch = in_sizes[0] / (IMG * IMG);
    dim3 grid(IMG / TH, batch);
    dilate9_kernel<<<grid, NTH>>>(in, out);
}

// round 8
// speedup vs baseline: 1.0791x; 1.0604x over previous
#include <cuda_runtime.h>
#include <math.h>

// 9x9 max-dilation, SAME padding with -inf border. Fused separable,
// 8 columns per thread (two float4), two 4-row Gil-Werman chunks per block:
//   - block = 1024 (full width) x 8 output rows; 4 warps x 32 lanes x 8 cols
//   - vertical 9-max in registers per chunk (suffix over 8 rows + streamed
//     prefix over 4 more), independent a/b 4-col pipelines
//   - horizontal 9-max: 8-wide prefix/suffix + 8 shuffles per row (serves
//     8 outputs); cross-warp edges via tiny double-buffered smem
//   - interior strips (1..126) use an unpredicated fast path
// Input 16x1024x1024x1 fp32.

#define IMG 1024
#define TH 8              // output rows per block
#define CH 4              // output rows per chunk
#define NTH 128
#define NW 4              // warps per block (4 x 256 cols = 1024)

__device__ __forceinline__ float4 max4(float4 a, float4 b) {
    return make_float4(fmaxf(a.x, b.x), fmaxf(a.y, b.y),
                       fmaxf(a.z, b.z), fmaxf(a.w, b.w));
}

#define NEGF4 make_float4(-INFINITY, -INFINITY, -INFINITY, -INFINITY)

template<bool GUARD>
__device__ __forceinline__ float4 ldrow(const float* __restrict__ img, int gy, int gx) {
    if (GUARD && (unsigned)gy >= (unsigned)IMG) return NEGF4;
    return *(const float4*)(img + (size_t)gy * IMG + gx);
}

template<bool GUARD>
__device__ __forceinline__ void process_strip(
    const float* __restrict__ img, float* __restrict__ oimg,
    int strip, int lane, int w,
    float4 (*eL)[NW][CH], float4 (*eR)[NW][CH])
{
    const int gx = w * 256 + lane * 8;    // first of this thread's 8 cols

    #pragma unroll
    for (int c = 0; c < 2; c++) {
        const int base = strip * TH + c * CH - 4;   // first raw row of chunk

        // ---- vertical: suffix maxes over raw rows base..base+7 (a|b halves) ----
        float4 ra[8], rb[8];
        #pragma unroll
        for (int j = 0; j < 8; j++) {
            ra[j] = ldrow<GUARD>(img, base + j, gx);
            rb[j] = ldrow<GUARD>(img, base + j, gx + 4);
        }
        const float4 ma47 = max4(max4(ra[4], ra[5]), max4(ra[6], ra[7]));
        const float4 Sa3 = max4(ra[3], ma47);
        const float4 Sa2 = max4(ra[2], Sa3);
        const float4 Sa1 = max4(ra[1], Sa2);
        const float4 Sa0 = max4(ra[0], Sa1);
        const float4 mb47 = max4(max4(rb[4], rb[5]), max4(rb[6], rb[7]));
        const float4 Sb3 = max4(rb[3], mb47);
        const float4 Sb2 = max4(rb[2], Sb3);
        const float4 Sb1 = max4(rb[1], Sb2);
        const float4 Sb0 = max4(rb[0], Sb1);

        // ---- vertical: streamed prefix over raw rows base+8..base+11 ----
        float4 vma[CH], vmb[CH];
        {
            float4 qa = ldrow<GUARD>(img, base + 8, gx);
            float4 qb = ldrow<GUARD>(img, base + 8, gx + 4);
            vma[0] = max4(Sa0, qa);  vmb[0] = max4(Sb0, qb);
            float4 na = ldrow<GUARD>(img, base + 9, gx);
            float4 nb = ldrow<GUARD>(img, base + 9, gx + 4);
            qa = max4(qa, na);  qb = max4(qb, nb);
            vma[1] = max4(Sa1, qa);  vmb[1] = max4(Sb1, qb);
            na = ldrow<GUARD>(img, base + 10, gx);
            nb = ldrow<GUARD>(img, base + 10, gx + 4);
            qa = max4(qa, na);  qb = max4(qb, nb);
            vma[2] = max4(Sa2, qa);  vmb[2] = max4(Sb2, qb);
            na = ldrow<GUARD>(img, base + 11, gx);
            nb = ldrow<GUARD>(img, base + 11, gx + 4);
            qa = max4(qa, na);  qb = max4(qb, nb);
            vma[3] = max4(Sa3, qa);  vmb[3] = max4(Sb3, qb);
        }

        // ---- cross-warp edge exchange (double-buffered by chunk) ----
        if (lane == 0) {                  // my va is the right-neighbor's left halo source
            #pragma unroll
            for (int t = 0; t < CH; t++) eL[c][w][t] = vma[t];
        }
        if (lane == 31) {                 // my vb is the left... right edge source
            #pragma unroll
            for (int t = 0; t < CH; t++) eR[c][w][t] = vmb[t];
        }
        __syncthreads();

        // ---- horizontal 9-max: 8-wide prefix/suffix + 8 shuffles ----
        #pragma unroll
        for (int t = 0; t < CH; t++) {
            const float4 a = vma[t];
            const float4 b = vmb[t];
            const float p0 = a.x;
            const float p1 = fmaxf(p0, a.y);
            const float p2 = fmaxf(p1, a.z);
            const float p3 = fmaxf(p2, a.w);
            const float p4 = fmaxf(p3, b.x);
            const float p5 = fmaxf(p4, b.y);
            const float p6 = fmaxf(p5, b.z);
            const float p7 = fmaxf(p6, b.w);
            const float s7 = b.w;
            const float s6 = fmaxf(b.z, s7);
            const float s5 = fmaxf(b.y, s6);
            const float s4 = fmaxf(b.x, s5);
            const float s3 = fmaxf(a.w, s4);
            const float s2 = fmaxf(a.z, s3);
            const float s1 = fmaxf(a.y, s2);
            const float s0 = p7;

            float sU4 = __shfl_up_sync(0xffffffffu, s4, 1);
            float sU5 = __shfl_up_sync(0xffffffffu, s5, 1);
            float sU6 = __shfl_up_sync(0xffffffffu, s6, 1);
            float sU7 = __shfl_up_sync(0xffffffffu, s7, 1);
            float pD0 = __shfl_down_sync(0xffffffffu, p0, 1);
            float pD1 = __shfl_down_sync(0xffffffffu, p1, 1);
            float pD2 = __shfl_down_sync(0xffffffffu, p2, 1);
            float pD3 = __shfl_down_sync(0xffffffffu, p3, 1);

            if (lane == 0) {   // left neighbor = warp w-1 lane 31's b-half (or border)
                const float4 hl = (w > 0) ? eR[c][w - 1][t] : NEGF4;
                sU7 = hl.w;
                sU6 = fmaxf(hl.z, sU7);
                sU5 = fmaxf(hl.y, sU6);
                sU4 = fmaxf(hl.x, sU5);
            }
            if (lane == 31) {  // right neighbor = warp w+1 lane 0's a-half (or border)
                const float4 hr = (w < NW - 1) ? eL[c][w + 1][t] : NEGF4;
                pD0 = hr.x;
                pD1 = fmaxf(pD0, hr.y);
                pD2 = fmaxf(pD1, hr.z);
                pD3 = fmaxf(pD2, hr.w);
            }

            float4 oa, ob;
            oa.x = fmaxf(sU4, p4);
            oa.y = fmaxf(sU5, p5);
            oa.z = fmaxf(sU6, p6);
            oa.w = fmaxf(sU7, p7);
            ob.x = fmaxf(s0, pD0);
            ob.y = fmaxf(s1, pD1);
            ob.z = fmaxf(s2, pD2);
            ob.w = fmaxf(s3, pD3);

            float* orow = oimg + (size_t)(strip * TH + c * CH + t) * IMG + gx;
            *(float4*)orow = oa;
            *(float4*)(orow + 4) = ob;
        }
    }
}

__global__ __launch_bounds__(NTH)
void dilate9_kernel(const float* __restrict__ in, float* __restrict__ out) {
    __shared__ __align__(16) float4 eL[2][NW][CH];
    __shared__ __align__(16) float4 eR[2][NW][CH];

    const int strip = blockIdx.x;     // 0..127 (8-row strips)
    const int bz    = blockIdx.y;     // batch
    const int tid   = threadIdx.x;
    const int lane  = tid & 31;
    const int w     = tid >> 5;

    const float* img = in  + (size_t)bz * IMG * IMG;
    float*      oimg = out + (size_t)bz * IMG * IMG;

    // strips 1..126: raw rows [strip*8-4, strip*8+11] all within [0,1024)
    if (strip >= 1 && strip <= 126)
        process_strip<false>(img, oimg, strip, lane, w, eL, eR);
    else
        process_strip<true>(img, oimg, strip, lane, w, eL, eR);
}

extern "C" void kernel_launch(void* const* d_in, const int* in_sizes, int n_in,
                              void* d_out, int out_size) {
    const float* in = (const float*)d_in[0];
    float* out = (float*)d_out;
    const int batch = in_sizes[0] / (IMG * IMG);
    dim3 grid(IMG / TH, batch);
    dilate9_kernel<<<grid, NTH>>>(in, out);
}